// round 10
// baseline (speedup 1.0000x reference)
#include <cuda_runtime.h>
#include <cuda_fp16.h>
#include <cstdint>

// ---------------------------------------------------------------- constants
#define BATCH 4
#define SEQ   4096
#define DM    1024
#define DI    2048
#define DS    16
#define NTAPS 32

// ---------------------------------------------------------------- scratch (device globals)
__device__ float  d_taps[DI*NTAPS];
__device__ __half d_xh   [(size_t)BATCH*SEQ*DM];   // input act fp16 [B*S][DM]
__device__ __half d_xp16 [(size_t)BATCH*SEQ*DI];   // in-proj fp16 [B*S][DI]
__device__ __half d_g16  [(size_t)BATCH*SEQ*DI];   // gate fp16 [B*S][DI]
__device__ __half d_yh   [(size_t)BATCH*SEQ*DI];   // fir*gate fp16 [B*S][DI]
__device__ __half d_win_h [(size_t)DI*DM];         // [N][K]
__device__ __half d_wg_h  [(size_t)DI*DM];
__device__ __half d_wout_h[(size_t)DM*DI];         // [N][K]

// ---------------------------------------------------------------- utils
__device__ __forceinline__ uint32_t smem_u32(const void* p) {
    uint32_t a;
    asm("{ .reg .u64 t; cvta.to.shared.u64 t, %1; cvt.u32.u64 %0, t; }"
        : "=r"(a) : "l"(p));
    return a;
}
__device__ __forceinline__ void cpa16(uint32_t dst, const void* src) {
    asm volatile("cp.async.cg.shared.global [%0], [%1], 16;"
                 :: "r"(dst), "l"(src) : "memory");
}
#define CP_COMMIT() asm volatile("cp.async.commit_group;" ::: "memory")
template<int N> __device__ __forceinline__ void cp_wait() {
    asm volatile("cp.async.wait_group %0;" :: "n"(N) : "memory");
}
__device__ __forceinline__ void ldmx4(uint32_t* r, uint32_t addr) {
    asm volatile("ldmatrix.sync.aligned.m8n8.x4.shared.b16 {%0,%1,%2,%3}, [%4];"
                 : "=r"(r[0]), "=r"(r[1]), "=r"(r[2]), "=r"(r[3]) : "r"(addr));
}
__device__ __forceinline__ void mma16816(float* c, const uint32_t* a,
                                         uint32_t b0, uint32_t b1) {
    asm volatile(
        "mma.sync.aligned.m16n8k16.row.col.f32.f16.f16.f32 "
        "{%0,%1,%2,%3}, {%4,%5,%6,%7}, {%8,%9}, {%0,%1,%2,%3};"
        : "+f"(c[0]), "+f"(c[1]), "+f"(c[2]), "+f"(c[3])
        : "r"(a[0]), "r"(a[1]), "r"(a[2]), "r"(a[3]), "r"(b0), "r"(b1));
}

// ---------------------------------------------------------------- merged preprocessing
// One kernel, 256-thread blocks, dispatch by flat blockIdx.x:
//   [0, 16384)            conv_x   : x f32 -> d_xh fp16 (1024 float4 per block)
//   [16384, 18432)        w_in     : [1024][2048] -> [2048][1024] fp16
//   [18432, 20480)        w_gate
//   [20480, 22528)        w_out    : [2048][1024] -> [1024][2048] fp16
//   [22528, 22536)        taps     : 256 channels per block
#define PREP_CONVX  16384
#define PREP_W0     (PREP_CONVX)
#define PREP_W1     (PREP_W0 + 2048)
#define PREP_W2     (PREP_W1 + 2048)
#define PREP_TAPS   (PREP_W2 + 2048)
#define PREP_TOTAL  (PREP_TAPS + 8)

__device__ __forceinline__ void prep_transpose(
    const float* __restrict__ W, __half* __restrict__ WT,
    int K, int N, int tile, float* tb /* [32][33] */)
{
    int nt = N >> 5;
    int n0 = (tile % nt) * 32, k0 = (tile / nt) * 32;
    int tx = threadIdx.x & 31, ty = threadIdx.x >> 5;
#pragma unroll
    for (int i = ty; i < 32; i += 8)
        tb[i * 33 + tx] = W[(size_t)(k0 + i) * N + n0 + tx];
    __syncthreads();
#pragma unroll
    for (int j = ty; j < 32; j += 8)
        WT[(size_t)(n0 + j) * K + k0 + tx] = __float2half_rn(tb[tx * 33 + j]);
}

__global__ __launch_bounds__(256) void prep_kernel(
    const float* __restrict__ x,
    const float* __restrict__ w_in, const float* __restrict__ w_gate,
    const float* __restrict__ w_out,
    const float* __restrict__ A, const float* __restrict__ B_ssm,
    const float* __restrict__ C_ssm)
{
    __shared__ float tb[32 * 33];
    const int bid = blockIdx.x;
    const int t = threadIdx.x;

    if (bid < PREP_CONVX) {
        size_t idx = (size_t)bid * 256 + t;
        float4 v = *(const float4*)(x + idx * 4);
        __half2 h0 = __floats2half2_rn(v.x, v.y);
        __half2 h1 = __floats2half2_rn(v.z, v.w);
        uint2 pk = { *(uint32_t*)&h0, *(uint32_t*)&h1 };
        *(uint2*)((__half*)d_xh + idx * 4) = pk;
    } else if (bid < PREP_W1) {
        prep_transpose(w_in, d_win_h, DM, DI, bid - PREP_W0, tb);
    } else if (bid < PREP_W2) {
        prep_transpose(w_gate, d_wg_h, DM, DI, bid - PREP_W1, tb);
    } else if (bid < PREP_TAPS) {
        prep_transpose(w_out, d_wout_h, DI, DM, bid - PREP_W2, tb);
    } else {
        int c = (bid - PREP_TAPS) * 256 + t;
        if (c < DI) {
            const float* Ac = A + (size_t)c * DS * DS;
            float v[DS], Cv[DS];
#pragma unroll
            for (int n = 0; n < DS; n++) {
                v[n] = B_ssm[c*DS+n]; Cv[n] = C_ssm[c*DS+n];
            }
            for (int j = 0; j < NTAPS; j++) {
                float y = 0.f;
#pragma unroll
                for (int n = 0; n < DS; n++) y = fmaf(Cv[n], v[n], y);
                d_taps[c*NTAPS + j] = y;
                float w[DS];
#pragma unroll
                for (int n = 0; n < DS; n++) {
                    float acc = 0.f;
#pragma unroll
                    for (int m = 0; m < DS; m++) acc = fmaf(Ac[n*DS+m], v[m], acc);
                    w[n] = acc;
                }
#pragma unroll
                for (int n = 0; n < DS; n++) v[n] = w[n];
            }
        }
    }
}

// ---------------------------------------------------------------- FIR + gate (all fp16 I/O, m-major)
__global__ __launch_bounds__(256) void fir_kernel()
{
    __shared__ float sx[288][33];       // [32 halo + 256][c]
    __shared__ float st[32][33];        // taps[c][j]
    const int t = threadIdx.x;
    const int c0 = blockIdx.y * 32, b = blockIdx.z;
    const int s0 = blockIdx.x * 256;
    const size_t rowbase = (size_t)b * SEQ;

    for (int idx = t; idx < 288 * 32; idx += 256) {
        int z = idx >> 5, c = idx & 31;
        int s = s0 - 32 + z;
        float v = 0.f;
        if (s >= 0) v = __half2float(d_xp16[(rowbase + s) * DI + c0 + c]);
        sx[z][c] = v;
    }
    for (int idx = t; idx < 32 * 32; idx += 256) {
        int r = idx >> 5, j = idx & 31;
        st[r][j] = d_taps[(c0 + r) * NTAPS + j];
    }
    __syncthreads();

    const int c  = t & 31;
    const int sb = (t >> 5) * 32;
    float k[NTAPS];
#pragma unroll
    for (int j = 0; j < NTAPS; j++) k[j] = st[c][j];

#pragma unroll
    for (int ch = 0; ch < 4; ch++) {
        const int sc = sb + ch * 8;
        float w[39];
#pragma unroll
        for (int z = 0; z < 39; z++) w[z] = sx[sc + 1 + z][c];
        float acc[8];
#pragma unroll
        for (int i = 0; i < 8; i++) acc[i] = 0.f;
#pragma unroll
        for (int j = 0; j < NTAPS; j++)
#pragma unroll
            for (int i = 0; i < 8; i++)
                acc[i] = fmaf(k[j], w[31 + i - j], acc[i]);
#pragma unroll
        for (int i = 0; i < 8; i++) {
            size_t row = rowbase + s0 + sc + i;
            float gv = __half2float(d_g16[row * DI + c0 + c]);
            d_yh[row * DI + c0 + c] = __float2half_rn(acc[i] * gv);
        }
    }
}

// ---------------------------------------------------------------- mma.sync GEMM (fp16)
// C[128x128] per CTA. A [M][K] fp16, B [N][K] fp16.
// BK=64 (128B rows, XOR-8 swizzle), 3-stage cp.async, 8 warps 64x32, 2 CTA/SM.
// Single __syncthreads per mainloop iteration (slot WAR separated by it).
#define BKB        128
#define STAGE_B    32768
#define NSTAGE     3
#define SMEM_GEMM  (NSTAGE * STAGE_B)

template<int KBASE>
__device__ __forceinline__ void load_stage(uint32_t sb, int slot,
                                           const char* Ac, const char* Bc)
{
    const int ld = KBASE * 2;
    uint32_t sA = sb + slot * STAGE_B;
    uint32_t sB = sA + 16384;
    const int t = threadIdx.x;
#pragma unroll
    for (int it = 0; it < 4; it++) {
        int idx = t + it * 256;
        int r = idx >> 3, c = idx & 7;
        cpa16(sA + r * BKB + ((c ^ (r & 7)) << 4), Ac + (size_t)r * ld + c * 16);
    }
#pragma unroll
    for (int it = 0; it < 4; it++) {
        int idx = t + it * 256;
        int r = idx >> 3, c = idx & 7;
        cpa16(sB + r * BKB + ((c ^ (r & 7)) << 4), Bc + (size_t)r * ld + c * 16);
    }
}

// EPI 0: A=d_xh, B=d_win_h/d_wg_h (dual), writes d_xp16 / d_g16 (m-major fp16).
// EPI 1: A=d_yh, B=d_wout_h, writes f32 out rows.
template<int EPI, int KBASE>
__global__ __launch_bounds__(256, 2) void gemm_mma(
    const float* __restrict__ bias0, const float* __restrict__ bias1,
    float* __restrict__ outp)
{
    extern __shared__ char smem[];
    uint32_t sb = smem_u32(smem);
    const int t   = threadIdx.x;
    const int wid = t >> 5, lid = t & 31;
    const int NKC = KBASE / 64;

    int sel, n0;
    const __half* Aglob;
    const __half* B;
    const float* bias;
    if (EPI == 0) {
        Aglob = d_xh;
        sel = (blockIdx.x >= DI / 128);
        n0  = (blockIdx.x & (DI / 128 - 1)) * 128;
        B = sel ? d_wg_h : d_win_h;
        bias = sel ? bias1 : bias0;
    } else {
        Aglob = d_yh;
        sel = 0;
        n0  = blockIdx.x * 128;
        B = d_wout_h;
        bias = bias0;
    }
    const int m0 = blockIdx.y * 128;
    const char* Abase = (const char*)(Aglob + (size_t)m0 * KBASE);
    const char* Bbase = (const char*)(B + (size_t)n0 * KBASE);

#pragma unroll
    for (int p = 0; p < NSTAGE - 1; p++) {
        load_stage<KBASE>(sb, p, Abase + p * 128, Bbase + p * 128);
        CP_COMMIT();
    }

    const int wm = (wid & 1) * 64;
    const int wn = (wid >> 1) * 32;

    float acc[4][4][4];
#pragma unroll
    for (int i = 0; i < 4; i++)
#pragma unroll
        for (int j = 0; j < 4; j++)
#pragma unroll
            for (int q = 0; q < 4; q++) acc[i][j][q] = 0.f;

    int slot = 0, slot_ld = NSTAGE - 1;
    for (int i = 0; i < NKC; i++) {
        cp_wait<NSTAGE - 2>();
        __syncthreads();                   // single barrier per iteration
        int j = i + NSTAGE - 1;
        if (j < NKC) {
            load_stage<KBASE>(sb, slot_ld, Abase + j * 128, Bbase + j * 128);
        }
        CP_COMMIT();
        if (++slot_ld == NSTAGE) slot_ld = 0;

        uint32_t sA = sb + slot * STAGE_B;
        uint32_t sB = sA + 16384;
        if (++slot == NSTAGE) slot = 0;
#pragma unroll
        for (int kk = 0; kk < 4; kk++) {
            uint32_t a[4][4], b[2][4];
#pragma unroll
            for (int mi = 0; mi < 4; mi++) {
                int row = wm + mi * 16 + (lid & 15);
                int ch  = kk * 2 + (lid >> 4);
                ldmx4(a[mi], sA + row * BKB + ((ch ^ (row & 7)) << 4));
            }
#pragma unroll
            for (int bi = 0; bi < 2; bi++) {
                int row = wn + bi * 16 + (lid & 15);
                int ch  = kk * 2 + (lid >> 4);
                ldmx4(b[bi], sB + row * BKB + ((ch ^ (row & 7)) << 4));
            }
#pragma unroll
            for (int mi = 0; mi < 4; mi++) {
#pragma unroll
                for (int bi = 0; bi < 2; bi++) {
                    mma16816(acc[mi][bi * 2 + 0], a[mi], b[bi][0], b[bi][2]);
                    mma16816(acc[mi][bi * 2 + 1], a[mi], b[bi][1], b[bi][3]);
                }
            }
        }
    }

    // ---- epilogue (R7 direct-store form) ----
    const int q4 = lid & 3;
    const int r8 = lid >> 2;

    if (EPI == 0) {
        __half* dst = sel ? d_g16 : d_xp16;
#pragma unroll
        for (int mi = 0; mi < 4; mi++) {
#pragma unroll
            for (int ni = 0; ni < 4; ni++) {
                int n = n0 + wn + ni * 8 + 2 * q4;
                float bz0 = bias[n], bz1 = bias[n + 1];
#pragma unroll
                for (int rr = 0; rr < 2; rr++) {
                    int m = m0 + wm + mi * 16 + r8 + rr * 8;
                    float v0 = acc[mi][ni][rr * 2 + 0] + bz0;
                    float v1 = acc[mi][ni][rr * 2 + 1] + bz1;
                    if (sel) {
                        v0 = 1.f / (1.f + __expf(-v0));
                        v1 = 1.f / (1.f + __expf(-v1));
                    }
                    __half2 h2 = __floats2half2_rn(v0, v1);
                    *(__half2*)(dst + (size_t)m * DI + n) = h2;
                }
            }
        }
    } else {
#pragma unroll
        for (int mi = 0; mi < 4; mi++) {
#pragma unroll
            for (int ni = 0; ni < 4; ni++) {
                int n = n0 + wn + ni * 8 + 2 * q4;
                float bz0 = bias[n], bz1 = bias[n + 1];
#pragma unroll
                for (int rr = 0; rr < 2; rr++) {
                    int m = m0 + wm + mi * 16 + r8 + rr * 8;
                    float2 v;
                    v.x = acc[mi][ni][rr * 2 + 0] + bz0;
                    v.y = acc[mi][ni][rr * 2 + 1] + bz1;
                    *(float2*)(outp + (size_t)m * DM + n) = v;
                }
            }
        }
    }
}

// ---------------------------------------------------------------- launch
extern "C" void kernel_launch(void* const* d_in, const int* in_sizes, int n_in,
                              void* d_out, int out_size)
{
    const float* x      = (const float*)d_in[0];
    const float* w_in   = (const float*)d_in[1];
    const float* b_in   = (const float*)d_in[2];
    const float* w_gate = (const float*)d_in[3];
    const float* b_gate = (const float*)d_in[4];
    const float* A      = (const float*)d_in[5];
    const float* B_ssm  = (const float*)d_in[6];
    const float* C_ssm  = (const float*)d_in[7];
    const float* w_out  = (const float*)d_in[8];
    const float* b_out  = (const float*)d_in[9];
    float* out = (float*)d_out;

    static bool attr_done = false;
    if (!attr_done) {
        cudaFuncSetAttribute(gemm_mma<0, DM>,
                             cudaFuncAttributeMaxDynamicSharedMemorySize, SMEM_GEMM);
        cudaFuncSetAttribute(gemm_mma<1, DI>,
                             cudaFuncAttributeMaxDynamicSharedMemorySize, SMEM_GEMM);
        attr_done = true;
    }

    prep_kernel<<<PREP_TOTAL, 256>>>(x, w_in, w_gate, w_out, A, B_ssm, C_ssm);

    gemm_mma<0, DM><<<dim3(2 * DI / 128, BATCH * SEQ / 128), 256, SMEM_GEMM>>>(
        b_in, b_gate, nullptr);

    fir_kernel<<<dim3(SEQ / 256, DI / 32, BATCH), 256>>>();

    gemm_mma<1, DI><<<dim3(DM / 128, BATCH * SEQ / 128), 256, SMEM_GEMM>>>(
        b_out, nullptr, out);
}

// round 11
// speedup vs baseline: 1.1265x; 1.1265x over previous
#include <cuda_runtime.h>
#include <cuda_fp16.h>
#include <cstdint>

// ---------------------------------------------------------------- constants
#define BATCH 4
#define SEQ   4096
#define DM    1024
#define DI    2048
#define DS    16
#define NTAPS 32

// ---------------------------------------------------------------- scratch (device globals)
__device__ float  d_taps[DI*NTAPS];
__device__ __half d_xh   [(size_t)BATCH*SEQ*DM];   // input act fp16 [B*S][DM]
__device__ __half d_xp16 [(size_t)BATCH*SEQ*DI];   // in-proj fp16 [B*S][DI]
__device__ __half d_g16  [(size_t)BATCH*SEQ*DI];   // gate fp16 [B*S][DI]
__device__ __half d_yh   [(size_t)BATCH*SEQ*DI];   // fir*gate fp16 [B*S][DI]
__device__ __half d_win_h [(size_t)DI*DM];         // [N][K]
__device__ __half d_wg_h  [(size_t)DI*DM];
__device__ __half d_wout_h[(size_t)DM*DI];         // [N][K]

// ---------------------------------------------------------------- utils
__device__ __forceinline__ uint32_t smem_u32(const void* p) {
    uint32_t a;
    asm("{ .reg .u64 t; cvta.to.shared.u64 t, %1; cvt.u32.u64 %0, t; }"
        : "=r"(a) : "l"(p));
    return a;
}
__device__ __forceinline__ void cpa16(uint32_t dst, const void* src) {
    asm volatile("cp.async.cg.shared.global [%0], [%1], 16;"
                 :: "r"(dst), "l"(src) : "memory");
}
#define CP_COMMIT() asm volatile("cp.async.commit_group;" ::: "memory")
template<int N> __device__ __forceinline__ void cp_wait() {
    asm volatile("cp.async.wait_group %0;" :: "n"(N) : "memory");
}
__device__ __forceinline__ void ldmx4(uint32_t* r, uint32_t addr) {
    asm volatile("ldmatrix.sync.aligned.m8n8.x4.shared.b16 {%0,%1,%2,%3}, [%4];"
                 : "=r"(r[0]), "=r"(r[1]), "=r"(r[2]), "=r"(r[3]) : "r"(addr));
}
__device__ __forceinline__ void mma16816(float* c, const uint32_t* a,
                                         uint32_t b0, uint32_t b1) {
    asm volatile(
        "mma.sync.aligned.m16n8k16.row.col.f32.f16.f16.f32 "
        "{%0,%1,%2,%3}, {%4,%5,%6,%7}, {%8,%9}, {%0,%1,%2,%3};"
        : "+f"(c[0]), "+f"(c[1]), "+f"(c[2]), "+f"(c[3])
        : "r"(a[0]), "r"(a[1]), "r"(a[2]), "r"(a[3]), "r"(b0), "r"(b1));
}

// ---------------------------------------------------------------- taps
__global__ __launch_bounds__(256) void taps_kernel(
    const float* __restrict__ A, const float* __restrict__ B_ssm,
    const float* __restrict__ C_ssm)
{
    int c = blockIdx.x * blockDim.x + threadIdx.x;
    if (c >= DI) return;
    const float* Ac = A + (size_t)c * DS * DS;
    float v[DS], Cv[DS];
#pragma unroll
    for (int n = 0; n < DS; n++) { v[n] = B_ssm[c*DS+n]; Cv[n] = C_ssm[c*DS+n]; }
    for (int j = 0; j < NTAPS; j++) {
        float y = 0.f;
#pragma unroll
        for (int n = 0; n < DS; n++) y = fmaf(Cv[n], v[n], y);
        d_taps[c*NTAPS + j] = y;
        float w[DS];
#pragma unroll
        for (int n = 0; n < DS; n++) {
            float acc = 0.f;
#pragma unroll
            for (int m = 0; m < DS; m++) acc = fmaf(Ac[n*DS+m], v[m], acc);
            w[n] = acc;
        }
#pragma unroll
        for (int n = 0; n < DS; n++) v[n] = w[n];
    }
}

// ---------------------------------------------------------------- x f32 -> fp16
__global__ __launch_bounds__(256) void conv_x_kernel(const float* __restrict__ x)
{
    size_t idx = (size_t)blockIdx.x * 256 + threadIdx.x;   // one float4
    float4 v = *(const float4*)(x + idx * 4);
    __half2 h0 = __floats2half2_rn(v.x, v.y);
    __half2 h1 = __floats2half2_rn(v.z, v.w);
    uint2 pk = { *(uint32_t*)&h0, *(uint32_t*)&h1 };
    *(uint2*)((__half*)d_xh + idx * 4) = pk;
}

// ---------------------------------------------------------------- W [K][N]f32 -> [N][K]fp16
template<int WHICH, int K, int N>
__global__ void conv_w_kernel(const float* __restrict__ W)
{
    __shared__ float tb[32][33];
    __half* WT = (WHICH == 0 ? d_win_h : WHICH == 1 ? d_wg_h : d_wout_h);
    int n0 = blockIdx.x * 32, k0 = blockIdx.y * 32;
    int tx = threadIdx.x, ty = threadIdx.y;
#pragma unroll
    for (int i = ty; i < 32; i += 8)
        tb[i][tx] = W[(size_t)(k0 + i) * N + n0 + tx];
    __syncthreads();
#pragma unroll
    for (int j = ty; j < 32; j += 8)
        WT[(size_t)(n0 + j) * K + k0 + tx] = __float2half_rn(tb[tx][j]);
}

// ---------------------------------------------------------------- FIR + gate (all fp16 I/O, m-major)
__global__ __launch_bounds__(256) void fir_kernel()
{
    __shared__ float sx[288][33];       // [32 halo + 256][c]
    __shared__ float st[32][33];        // taps[c][j]
    const int t = threadIdx.x;
    const int c0 = blockIdx.y * 32, b = blockIdx.z;
    const int s0 = blockIdx.x * 256;
    const size_t rowbase = (size_t)b * SEQ;

    for (int idx = t; idx < 288 * 32; idx += 256) {
        int z = idx >> 5, c = idx & 31;
        int s = s0 - 32 + z;
        float v = 0.f;
        if (s >= 0) v = __half2float(d_xp16[(rowbase + s) * DI + c0 + c]);
        sx[z][c] = v;
    }
    for (int idx = t; idx < 32 * 32; idx += 256) {
        int r = idx >> 5, j = idx & 31;
        st[r][j] = d_taps[(c0 + r) * NTAPS + j];
    }
    __syncthreads();

    const int c  = t & 31;
    const int sb = (t >> 5) * 32;
    float k[NTAPS];
#pragma unroll
    for (int j = 0; j < NTAPS; j++) k[j] = st[c][j];

#pragma unroll
    for (int ch = 0; ch < 4; ch++) {
        const int sc = sb + ch * 8;
        float w[39];
#pragma unroll
        for (int z = 0; z < 39; z++) w[z] = sx[sc + 1 + z][c];
        float acc[8];
#pragma unroll
        for (int i = 0; i < 8; i++) acc[i] = 0.f;
#pragma unroll
        for (int j = 0; j < NTAPS; j++)
#pragma unroll
            for (int i = 0; i < 8; i++)
                acc[i] = fmaf(k[j], w[31 + i - j], acc[i]);
#pragma unroll
        for (int i = 0; i < 8; i++) {
            size_t row = rowbase + s0 + sc + i;
            float gv = __half2float(d_g16[row * DI + c0 + c]);
            d_yh[row * DI + c0 + c] = __float2half_rn(acc[i] * gv);
        }
    }
}

// ---------------------------------------------------------------- mma.sync GEMM (fp16)
// C[128x128] per CTA. A [M][K] fp16, B [N][K] fp16.
// BK=64 (128B rows, XOR-8 swizzle), 3-stage cp.async, 8 warps 64x32, 2 CTA/SM.
// Two __syncthreads per mainloop iteration (empirically fastest: keeps the two
// co-resident CTAs' warps in lockstep so cp_wait rarely exposes latency).
#define BKB        128
#define STAGE_B    32768
#define NSTAGE     3
#define SMEM_GEMM  (NSTAGE * STAGE_B)

template<int KBASE>
__device__ __forceinline__ void load_stage(uint32_t sb, int slot,
                                           const char* Ac, const char* Bc)
{
    const int ld = KBASE * 2;
    uint32_t sA = sb + slot * STAGE_B;
    uint32_t sB = sA + 16384;
    const int t = threadIdx.x;
#pragma unroll
    for (int it = 0; it < 4; it++) {
        int idx = t + it * 256;
        int r = idx >> 3, c = idx & 7;
        cpa16(sA + r * BKB + ((c ^ (r & 7)) << 4), Ac + (size_t)r * ld + c * 16);
    }
#pragma unroll
    for (int it = 0; it < 4; it++) {
        int idx = t + it * 256;
        int r = idx >> 3, c = idx & 7;
        cpa16(sB + r * BKB + ((c ^ (r & 7)) << 4), Bc + (size_t)r * ld + c * 16);
    }
}

// EPI 0: A=d_xh, B=d_win_h/d_wg_h (dual), writes d_xp16 / d_g16 (m-major fp16).
// EPI 1: A=d_yh, B=d_wout_h, writes f32 out rows.
template<int EPI, int KBASE>
__global__ __launch_bounds__(256, 2) void gemm_mma(
    const float* __restrict__ bias0, const float* __restrict__ bias1,
    float* __restrict__ outp)
{
    extern __shared__ char smem[];
    uint32_t sb = smem_u32(smem);
    const int t   = threadIdx.x;
    const int wid = t >> 5, lid = t & 31;
    const int NKC = KBASE / 64;

    int sel, n0;
    const __half* Aglob;
    const __half* B;
    const float* bias;
    if (EPI == 0) {
        Aglob = d_xh;
        sel = (blockIdx.x >= DI / 128);
        n0  = (blockIdx.x & (DI / 128 - 1)) * 128;
        B = sel ? d_wg_h : d_win_h;
        bias = sel ? bias1 : bias0;
    } else {
        Aglob = d_yh;
        sel = 0;
        n0  = blockIdx.x * 128;
        B = d_wout_h;
        bias = bias0;
    }
    const int m0 = blockIdx.y * 128;
    const char* Abase = (const char*)(Aglob + (size_t)m0 * KBASE);
    const char* Bbase = (const char*)(B + (size_t)n0 * KBASE);

#pragma unroll
    for (int p = 0; p < NSTAGE - 1; p++) {
        load_stage<KBASE>(sb, p, Abase + p * 128, Bbase + p * 128);
        CP_COMMIT();
    }

    const int wm = (wid & 1) * 64;
    const int wn = (wid >> 1) * 32;

    float acc[4][4][4];
#pragma unroll
    for (int i = 0; i < 4; i++)
#pragma unroll
        for (int j = 0; j < 4; j++)
#pragma unroll
            for (int q = 0; q < 4; q++) acc[i][j][q] = 0.f;

    int slot = 0, slot_ld = NSTAGE - 1;
    for (int i = 0; i < NKC; i++) {
        cp_wait<NSTAGE - 2>();
        __syncthreads();
        int j = i + NSTAGE - 1;
        if (j < NKC) {
            load_stage<KBASE>(sb, slot_ld, Abase + j * 128, Bbase + j * 128);
        }
        CP_COMMIT();
        if (++slot_ld == NSTAGE) slot_ld = 0;

        uint32_t sA = sb + slot * STAGE_B;
        uint32_t sB = sA + 16384;
        if (++slot == NSTAGE) slot = 0;
#pragma unroll
        for (int kk = 0; kk < 4; kk++) {
            uint32_t a[4][4], b[2][4];
#pragma unroll
            for (int mi = 0; mi < 4; mi++) {
                int row = wm + mi * 16 + (lid & 15);
                int ch  = kk * 2 + (lid >> 4);
                ldmx4(a[mi], sA + row * BKB + ((ch ^ (row & 7)) << 4));
            }
#pragma unroll
            for (int bi = 0; bi < 2; bi++) {
                int row = wn + bi * 16 + (lid & 15);
                int ch  = kk * 2 + (lid >> 4);
                ldmx4(b[bi], sB + row * BKB + ((ch ^ (row & 7)) << 4));
            }
#pragma unroll
            for (int mi = 0; mi < 4; mi++) {
#pragma unroll
                for (int bi = 0; bi < 2; bi++) {
                    mma16816(acc[mi][bi * 2 + 0], a[mi], b[bi][0], b[bi][2]);
                    mma16816(acc[mi][bi * 2 + 1], a[mi], b[bi][1], b[bi][3]);
                }
            }
        }
        __syncthreads();
    }

    // ---- epilogue ----
    const int q4 = lid & 3;
    const int r8 = lid >> 2;

    if (EPI == 0) {
        __half* dst = sel ? d_g16 : d_xp16;
#pragma unroll
        for (int mi = 0; mi < 4; mi++) {
#pragma unroll
            for (int ni = 0; ni < 4; ni++) {
                int n = n0 + wn + ni * 8 + 2 * q4;
                float bz0 = bias[n], bz1 = bias[n + 1];
#pragma unroll
                for (int rr = 0; rr < 2; rr++) {
                    int m = m0 + wm + mi * 16 + r8 + rr * 8;
                    float v0 = acc[mi][ni][rr * 2 + 0] + bz0;
                    float v1 = acc[mi][ni][rr * 2 + 1] + bz1;
                    if (sel) {
                        v0 = 1.f / (1.f + __expf(-v0));
                        v1 = 1.f / (1.f + __expf(-v1));
                    }
                    __half2 h2 = __floats2half2_rn(v0, v1);
                    *(__half2*)(dst + (size_t)m * DI + n) = h2;
                }
            }
        }
    } else {
#pragma unroll
        for (int mi = 0; mi < 4; mi++) {
#pragma unroll
            for (int ni = 0; ni < 4; ni++) {
                int n = n0 + wn + ni * 8 + 2 * q4;
                float bz0 = bias[n], bz1 = bias[n + 1];
#pragma unroll
                for (int rr = 0; rr < 2; rr++) {
                    int m = m0 + wm + mi * 16 + r8 + rr * 8;
                    float2 v;
                    v.x = acc[mi][ni][rr * 2 + 0] + bz0;
                    v.y = acc[mi][ni][rr * 2 + 1] + bz1;
                    *(float2*)(outp + (size_t)m * DM + n) = v;
                }
            }
        }
    }
}

// ---------------------------------------------------------------- launch
extern "C" void kernel_launch(void* const* d_in, const int* in_sizes, int n_in,
                              void* d_out, int out_size)
{
    const float* x      = (const float*)d_in[0];
    const float* w_in   = (const float*)d_in[1];
    const float* b_in   = (const float*)d_in[2];
    const float* w_gate = (const float*)d_in[3];
    const float* b_gate = (const float*)d_in[4];
    const float* A      = (const float*)d_in[5];
    const float* B_ssm  = (const float*)d_in[6];
    const float* C_ssm  = (const float*)d_in[7];
    const float* w_out  = (const float*)d_in[8];
    const float* b_out  = (const float*)d_in[9];
    float* out = (float*)d_out;

    static bool attr_done = false;
    if (!attr_done) {
        cudaFuncSetAttribute(gemm_mma<0, DM>,
                             cudaFuncAttributeMaxDynamicSharedMemorySize, SMEM_GEMM);
        cudaFuncSetAttribute(gemm_mma<1, DI>,
                             cudaFuncAttributeMaxDynamicSharedMemorySize, SMEM_GEMM);
        attr_done = true;
    }

    taps_kernel<<<DI / 256, 256>>>(A, B_ssm, C_ssm);
    conv_x_kernel<<<(BATCH * SEQ * DM / 4) / 256, 256>>>(x);
    conv_w_kernel<0, DM, DI><<<dim3(DI / 32, DM / 32), dim3(32, 8)>>>(w_in);
    conv_w_kernel<1, DM, DI><<<dim3(DI / 32, DM / 32), dim3(32, 8)>>>(w_gate);
    conv_w_kernel<2, DI, DM><<<dim3(DM / 32, DI / 32), dim3(32, 8)>>>(w_out);

    gemm_mma<0, DM><<<dim3(2 * DI / 128, BATCH * SEQ / 128), 256, SMEM_GEMM>>>(
        b_in, b_gate, nullptr);

    fir_kernel<<<dim3(SEQ / 256, DI / 32, BATCH), 256>>>();

    gemm_mma<1, DI><<<dim3(DM / 128, BATCH * SEQ / 128), 256, SMEM_GEMM>>>(
        b_out, nullptr, out);
}

// round 12
// speedup vs baseline: 1.1335x; 1.0062x over previous
#include <cuda_runtime.h>
#include <cuda_fp16.h>
#include <cstdint>

// ---------------------------------------------------------------- constants
#define BATCH 4
#define SEQ   4096
#define DM    1024
#define DI    2048
#define DS    16
#define NTAPS 32

// ---------------------------------------------------------------- scratch (device globals)
__device__ float  d_taps[DI*NTAPS];
__device__ __half d_xh   [(size_t)BATCH*SEQ*DM];   // input act fp16 [B*S][DM]
__device__ __half d_xp16 [(size_t)BATCH*SEQ*DI];   // in-proj fp16 [B*S][DI]
__device__ __half d_g16  [(size_t)BATCH*SEQ*DI];   // gate fp16 [B*S][DI]
__device__ __half d_yh   [(size_t)BATCH*SEQ*DI];   // fir*gate fp16 [B*S][DI]
__device__ __half d_win_h [(size_t)DI*DM];         // [N][K]
__device__ __half d_wg_h  [(size_t)DI*DM];
__device__ __half d_wout_h[(size_t)DM*DI];         // [N][K]

// ---------------------------------------------------------------- utils
__device__ __forceinline__ uint32_t smem_u32(const void* p) {
    uint32_t a;
    asm("{ .reg .u64 t; cvta.to.shared.u64 t, %1; cvt.u32.u64 %0, t; }"
        : "=r"(a) : "l"(p));
    return a;
}
__device__ __forceinline__ void cpa16(uint32_t dst, const void* src) {
    asm volatile("cp.async.cg.shared.global [%0], [%1], 16;"
                 :: "r"(dst), "l"(src) : "memory");
}
#define CP_COMMIT() asm volatile("cp.async.commit_group;" ::: "memory")
template<int N> __device__ __forceinline__ void cp_wait() {
    asm volatile("cp.async.wait_group %0;" :: "n"(N) : "memory");
}
__device__ __forceinline__ void ldmx4(uint32_t* r, uint32_t addr) {
    asm volatile("ldmatrix.sync.aligned.m8n8.x4.shared.b16 {%0,%1,%2,%3}, [%4];"
                 : "=r"(r[0]), "=r"(r[1]), "=r"(r[2]), "=r"(r[3]) : "r"(addr));
}
__device__ __forceinline__ void mma16816(float* c, const uint32_t* a,
                                         uint32_t b0, uint32_t b1) {
    asm volatile(
        "mma.sync.aligned.m16n8k16.row.col.f32.f16.f16.f32 "
        "{%0,%1,%2,%3}, {%4,%5,%6,%7}, {%8,%9}, {%0,%1,%2,%3};"
        : "+f"(c[0]), "+f"(c[1]), "+f"(c[2]), "+f"(c[3])
        : "r"(a[0]), "r"(a[1]), "r"(a[2]), "r"(a[3]), "r"(b0), "r"(b1));
}

// ---------------------------------------------------------------- taps
__global__ __launch_bounds__(256) void taps_kernel(
    const float* __restrict__ A, const float* __restrict__ B_ssm,
    const float* __restrict__ C_ssm)
{
    int c = blockIdx.x * blockDim.x + threadIdx.x;
    if (c >= DI) return;
    const float* Ac = A + (size_t)c * DS * DS;
    float v[DS], Cv[DS];
#pragma unroll
    for (int n = 0; n < DS; n++) { v[n] = B_ssm[c*DS+n]; Cv[n] = C_ssm[c*DS+n]; }
    for (int j = 0; j < NTAPS; j++) {
        float y = 0.f;
#pragma unroll
        for (int n = 0; n < DS; n++) y = fmaf(Cv[n], v[n], y);
        d_taps[c*NTAPS + j] = y;
        float w[DS];
#pragma unroll
        for (int n = 0; n < DS; n++) {
            float acc = 0.f;
#pragma unroll
            for (int m = 0; m < DS; m++) acc = fmaf(Ac[n*DS+m], v[m], acc);
            w[n] = acc;
        }
#pragma unroll
        for (int n = 0; n < DS; n++) v[n] = w[n];
    }
}

// ---------------------------------------------------------------- x f32 -> fp16
__global__ __launch_bounds__(256) void conv_x_kernel(const float* __restrict__ x)
{
    size_t idx = (size_t)blockIdx.x * 256 + threadIdx.x;   // one float4
    float4 v = *(const float4*)(x + idx * 4);
    __half2 h0 = __floats2half2_rn(v.x, v.y);
    __half2 h1 = __floats2half2_rn(v.z, v.w);
    uint2 pk = { *(uint32_t*)&h0, *(uint32_t*)&h1 };
    *(uint2*)((__half*)d_xh + idx * 4) = pk;
}

// ---------------------------------------------------------------- W [K][N]f32 -> [N][K]fp16
template<int WHICH, int K, int N>
__global__ void conv_w_kernel(const float* __restrict__ W)
{
    __shared__ float tb[32][33];
    __half* WT = (WHICH == 0 ? d_win_h : WHICH == 1 ? d_wg_h : d_wout_h);
    int n0 = blockIdx.x * 32, k0 = blockIdx.y * 32;
    int tx = threadIdx.x, ty = threadIdx.y;
#pragma unroll
    for (int i = ty; i < 32; i += 8)
        tb[i][tx] = W[(size_t)(k0 + i) * N + n0 + tx];
    __syncthreads();
#pragma unroll
    for (int j = ty; j < 32; j += 8)
        WT[(size_t)(n0 + j) * K + k0 + tx] = __float2half_rn(tb[tx][j]);
}

// ---------------------------------------------------------------- FIR + gate (all fp16 I/O, m-major)
__global__ __launch_bounds__(256) void fir_kernel()
{
    __shared__ float sx[288][33];       // [32 halo + 256][c]
    __shared__ float st[32][33];        // taps[c][j]
    const int t = threadIdx.x;
    const int c0 = blockIdx.y * 32, b = blockIdx.z;
    const int s0 = blockIdx.x * 256;
    const size_t rowbase = (size_t)b * SEQ;

    for (int idx = t; idx < 288 * 32; idx += 256) {
        int z = idx >> 5, c = idx & 31;
        int s = s0 - 32 + z;
        float v = 0.f;
        if (s >= 0) v = __half2float(d_xp16[(rowbase + s) * DI + c0 + c]);
        sx[z][c] = v;
    }
    for (int idx = t; idx < 32 * 32; idx += 256) {
        int r = idx >> 5, j = idx & 31;
        st[r][j] = d_taps[(c0 + r) * NTAPS + j];
    }
    __syncthreads();

    const int c  = t & 31;
    const int sb = (t >> 5) * 32;
    float k[NTAPS];
#pragma unroll
    for (int j = 0; j < NTAPS; j++) k[j] = st[c][j];

#pragma unroll
    for (int ch = 0; ch < 4; ch++) {
        const int sc = sb + ch * 8;
        float w[39];
#pragma unroll
        for (int z = 0; z < 39; z++) w[z] = sx[sc + 1 + z][c];
        float acc[8];
#pragma unroll
        for (int i = 0; i < 8; i++) acc[i] = 0.f;
#pragma unroll
        for (int j = 0; j < NTAPS; j++)
#pragma unroll
            for (int i = 0; i < 8; i++)
                acc[i] = fmaf(k[j], w[31 + i - j], acc[i]);
#pragma unroll
        for (int i = 0; i < 8; i++) {
            size_t row = rowbase + s0 + sc + i;
            float gv = __half2float(d_g16[row * DI + c0 + c]);
            d_yh[row * DI + c0 + c] = __float2half_rn(acc[i] * gv);
        }
    }
}

// ---------------------------------------------------------------- mma.sync GEMM (fp16)
// C[128x128] per CTA. A [M][K] fp16, B [N][K] fp16.
// BK=64 (128B rows, XOR-8 swizzle), 3-stage cp.async, 8 warps 64x32, 2 CTA/SM.
// Two __syncthreads per mainloop iteration (empirically fastest).
#define BKB        128
#define STAGE_B    32768
#define NSTAGE     3
#define SMEM_GEMM  (NSTAGE * STAGE_B)

template<int KBASE>
__device__ __forceinline__ void load_stage(uint32_t sb, int slot,
                                           const char* Ac, const char* Bc)
{
    const int ld = KBASE * 2;
    uint32_t sA = sb + slot * STAGE_B;
    uint32_t sB = sA + 16384;
    const int t = threadIdx.x;
#pragma unroll
    for (int it = 0; it < 4; it++) {
        int idx = t + it * 256;
        int r = idx >> 3, c = idx & 7;
        cpa16(sA + r * BKB + ((c ^ (r & 7)) << 4), Ac + (size_t)r * ld + c * 16);
    }
#pragma unroll
    for (int it = 0; it < 4; it++) {
        int idx = t + it * 256;
        int r = idx >> 3, c = idx & 7;
        cpa16(sB + r * BKB + ((c ^ (r & 7)) << 4), Bc + (size_t)r * ld + c * 16);
    }
}

// EPI 0: A=d_xh, B=d_win_h/d_wg_h (dual), writes d_xp16 / d_g16 (m-major fp16).
// EPI 1: A=d_yh, B=d_wout_h, writes f32 out rows.
template<int EPI, int KBASE>
__global__ __launch_bounds__(256, 2) void gemm_mma(
    const float* __restrict__ bias0, const float* __restrict__ bias1,
    float* __restrict__ outp)
{
    extern __shared__ char smem[];
    uint32_t sb = smem_u32(smem);
    const int t   = threadIdx.x;
    const int wid = t >> 5, lid = t & 31;
    const int NKC = KBASE / 64;

    int sel, n0;
    const __half* Aglob;
    const __half* B;
    const float* bias;
    if (EPI == 0) {
        Aglob = d_xh;
        sel = (blockIdx.x >= DI / 128);
        n0  = (blockIdx.x & (DI / 128 - 1)) * 128;
        B = sel ? d_wg_h : d_win_h;
        bias = sel ? bias1 : bias0;
    } else {
        Aglob = d_yh;
        sel = 0;
        n0  = blockIdx.x * 128;
        B = d_wout_h;
        bias = bias0;
    }
    const int m0 = blockIdx.y * 128;
    const char* Abase = (const char*)(Aglob + (size_t)m0 * KBASE);
    const char* Bbase = (const char*)(B + (size_t)n0 * KBASE);

#pragma unroll
    for (int p = 0; p < NSTAGE - 1; p++) {
        load_stage<KBASE>(sb, p, Abase + p * 128, Bbase + p * 128);
        CP_COMMIT();
    }

    const int wm = (wid & 1) * 64;
    const int wn = (wid >> 1) * 32;

    float acc[4][4][4];
#pragma unroll
    for (int i = 0; i < 4; i++)
#pragma unroll
        for (int j = 0; j < 4; j++)
#pragma unroll
            for (int q = 0; q < 4; q++) acc[i][j][q] = 0.f;

    int slot = 0, slot_ld = NSTAGE - 1;
    for (int i = 0; i < NKC; i++) {
        cp_wait<NSTAGE - 2>();
        __syncthreads();
        int j = i + NSTAGE - 1;
        if (j < NKC) {
            load_stage<KBASE>(sb, slot_ld, Abase + j * 128, Bbase + j * 128);
        }
        CP_COMMIT();
        if (++slot_ld == NSTAGE) slot_ld = 0;

        uint32_t sA = sb + slot * STAGE_B;
        uint32_t sB = sA + 16384;
        if (++slot == NSTAGE) slot = 0;
#pragma unroll
        for (int kk = 0; kk < 4; kk++) {
            uint32_t a[4][4], b[2][4];
#pragma unroll
            for (int mi = 0; mi < 4; mi++) {
                int row = wm + mi * 16 + (lid & 15);
                int ch  = kk * 2 + (lid >> 4);
                ldmx4(a[mi], sA + row * BKB + ((ch ^ (row & 7)) << 4));
            }
#pragma unroll
            for (int bi = 0; bi < 2; bi++) {
                int row = wn + bi * 16 + (lid & 15);
                int ch  = kk * 2 + (lid >> 4);
                ldmx4(b[bi], sB + row * BKB + ((ch ^ (row & 7)) << 4));
            }
#pragma unroll
            for (int mi = 0; mi < 4; mi++) {
#pragma unroll
                for (int bi = 0; bi < 2; bi++) {
                    mma16816(acc[mi][bi * 2 + 0], a[mi], b[bi][0], b[bi][2]);
                    mma16816(acc[mi][bi * 2 + 1], a[mi], b[bi][1], b[bi][3]);
                }
            }
        }
        __syncthreads();
    }

    // ---- epilogue ----
    const int q4 = lid & 3;
    const int r8 = lid >> 2;

    if (EPI == 0) {
        __half* dst = sel ? d_g16 : d_xp16;
#pragma unroll
        for (int mi = 0; mi < 4; mi++) {
#pragma unroll
            for (int ni = 0; ni < 4; ni++) {
                int n = n0 + wn + ni * 8 + 2 * q4;
                float bz0 = bias[n], bz1 = bias[n + 1];
#pragma unroll
                for (int rr = 0; rr < 2; rr++) {
                    int m = m0 + wm + mi * 16 + r8 + rr * 8;
                    float v0 = acc[mi][ni][rr * 2 + 0] + bz0;
                    float v1 = acc[mi][ni][rr * 2 + 1] + bz1;
                    if (sel) {
                        v0 = 1.f / (1.f + __expf(-v0));
                        v1 = 1.f / (1.f + __expf(-v1));
                    }
                    __half2 h2 = __floats2half2_rn(v0, v1);
                    *(__half2*)(dst + (size_t)m * DI + n) = h2;
                }
            }
        }
    } else {
#pragma unroll
        for (int mi = 0; mi < 4; mi++) {
#pragma unroll
            for (int ni = 0; ni < 4; ni++) {
                int n = n0 + wn + ni * 8 + 2 * q4;
                float bz0 = bias[n], bz1 = bias[n + 1];
#pragma unroll
                for (int rr = 0; rr < 2; rr++) {
                    int m = m0 + wm + mi * 16 + r8 + rr * 8;
                    float2 v;
                    v.x = acc[mi][ni][rr * 2 + 0] + bz0;
                    v.y = acc[mi][ni][rr * 2 + 1] + bz1;
                    *(float2*)(outp + (size_t)m * DM + n) = v;
                }
            }
        }
    }
}

// ---------------------------------------------------------------- launch
extern "C" void kernel_launch(void* const* d_in, const int* in_sizes, int n_in,
                              void* d_out, int out_size)
{
    const float* x      = (const float*)d_in[0];
    const float* w_in   = (const float*)d_in[1];
    const float* b_in   = (const float*)d_in[2];
    const float* w_gate = (const float*)d_in[3];
    const float* b_gate = (const float*)d_in[4];
    const float* A      = (const float*)d_in[5];
    const float* B_ssm  = (const float*)d_in[6];
    const float* C_ssm  = (const float*)d_in[7];
    const float* w_out  = (const float*)d_in[8];
    const float* b_out  = (const float*)d_in[9];
    float* out = (float*)d_out;

    static cudaStream_t s1 = nullptr, s2 = nullptr, s3 = nullptr;
    static cudaEvent_t evf = nullptr, ev1 = nullptr, ev2 = nullptr, ev3 = nullptr;
    static bool init_done = false;
    if (!init_done) {
        cudaFuncSetAttribute(gemm_mma<0, DM>,
                             cudaFuncAttributeMaxDynamicSharedMemorySize, SMEM_GEMM);
        cudaFuncSetAttribute(gemm_mma<1, DI>,
                             cudaFuncAttributeMaxDynamicSharedMemorySize, SMEM_GEMM);
        cudaStreamCreateWithFlags(&s1, cudaStreamNonBlocking);
        cudaStreamCreateWithFlags(&s2, cudaStreamNonBlocking);
        cudaStreamCreateWithFlags(&s3, cudaStreamNonBlocking);
        cudaEventCreateWithFlags(&evf, cudaEventDisableTiming);
        cudaEventCreateWithFlags(&ev1, cudaEventDisableTiming);
        cudaEventCreateWithFlags(&ev2, cudaEventDisableTiming);
        cudaEventCreateWithFlags(&ev3, cudaEventDisableTiming);
        init_done = true;
    }

    // fork side streams off the (per-thread default) capture stream
    cudaEventRecord(evf, cudaStreamPerThread);
    cudaStreamWaitEvent(s1, evf, 0);
    cudaStreamWaitEvent(s2, evf, 0);
    cudaStreamWaitEvent(s3, evf, 0);

    // prep: conv_x on main stream, weight transposes + taps in parallel
    conv_w_kernel<0, DM, DI><<<dim3(DI / 32, DM / 32), dim3(32, 8), 0, s1>>>(w_in);
    conv_w_kernel<1, DM, DI><<<dim3(DI / 32, DM / 32), dim3(32, 8), 0, s2>>>(w_gate);
    conv_w_kernel<2, DI, DM><<<dim3(DM / 32, DI / 32), dim3(32, 8), 0, s3>>>(w_out);
    taps_kernel<<<DI / 256, 256, 0, s3>>>(A, B_ssm, C_ssm);
    conv_x_kernel<<<(BATCH * SEQ * DM / 4) / 256, 256>>>(x);

    // join
    cudaEventRecord(ev1, s1);
    cudaEventRecord(ev2, s2);
    cudaEventRecord(ev3, s3);
    cudaStreamWaitEvent(cudaStreamPerThread, ev1, 0);
    cudaStreamWaitEvent(cudaStreamPerThread, ev2, 0);
    cudaStreamWaitEvent(cudaStreamPerThread, ev3, 0);

    gemm_mma<0, DM><<<dim3(2 * DI / 128, BATCH * SEQ / 128), 256, SMEM_GEMM>>>(
        b_in, b_gate, nullptr);

    fir_kernel<<<dim3(SEQ / 256, DI / 32, BATCH), 256>>>();

    gemm_mma<1, DI><<<dim3(DM / 128, BATCH * SEQ / 128), 256, SMEM_GEMM>>>(
        b_out, nullptr, out);
}

// round 13
// speedup vs baseline: 1.2269x; 1.0823x over previous
#include <cuda_runtime.h>
#include <cuda_fp16.h>
#include <cstdint>

// ---------------------------------------------------------------- constants
#define BATCH 4
#define SEQ   4096
#define DM    1024
#define DI    2048
#define DS    16
#define NTAPS 32

// ---------------------------------------------------------------- scratch (device globals)
__device__ float  d_taps[DI*NTAPS];
__device__ __half d_xh   [(size_t)BATCH*SEQ*DM];   // input act fp16 [B*S][DM]
__device__ __half d_xp16 [(size_t)BATCH*SEQ*DI];   // in-proj fp16 [B*S][DI]
__device__ __half d_g16  [(size_t)BATCH*SEQ*DI];   // gate fp16 [B*S][DI]
__device__ __half d_yh   [(size_t)BATCH*SEQ*DI];   // fir*gate fp16 [B*S][DI]
__device__ __half d_win_h [(size_t)DI*DM];         // [N][K]
__device__ __half d_wg_h  [(size_t)DI*DM];
__device__ __half d_wout_h[(size_t)DM*DI];         // [N][K]

// ---------------------------------------------------------------- utils
__device__ __forceinline__ uint32_t smem_u32(const void* p) {
    uint32_t a;
    asm("{ .reg .u64 t; cvta.to.shared.u64 t, %1; cvt.u32.u64 %0, t; }"
        : "=r"(a) : "l"(p));
    return a;
}
__device__ __forceinline__ void cpa16(uint32_t dst, const void* src) {
    asm volatile("cp.async.cg.shared.global [%0], [%1], 16;"
                 :: "r"(dst), "l"(src) : "memory");
}
#define CP_COMMIT() asm volatile("cp.async.commit_group;" ::: "memory")
template<int N> __device__ __forceinline__ void cp_wait() {
    asm volatile("cp.async.wait_group %0;" :: "n"(N) : "memory");
}
__device__ __forceinline__ void ldmx4(uint32_t* r, uint32_t addr) {
    asm volatile("ldmatrix.sync.aligned.m8n8.x4.shared.b16 {%0,%1,%2,%3}, [%4];"
                 : "=r"(r[0]), "=r"(r[1]), "=r"(r[2]), "=r"(r[3]) : "r"(addr));
}
__device__ __forceinline__ void mma16816(float* c, const uint32_t* a,
                                         uint32_t b0, uint32_t b1) {
    asm volatile(
        "mma.sync.aligned.m16n8k16.row.col.f32.f16.f16.f32 "
        "{%0,%1,%2,%3}, {%4,%5,%6,%7}, {%8,%9}, {%0,%1,%2,%3};"
        : "+f"(c[0]), "+f"(c[1]), "+f"(c[2]), "+f"(c[3])
        : "r"(a[0]), "r"(a[1]), "r"(a[2]), "r"(a[3]), "r"(b0), "r"(b1));
}

// ---------------------------------------------------------------- taps (16 threads/channel)
// Lane n of each 16-lane group owns state element n: A-row n in regs, v/Cv scalar.
// y = C.v via width-16 shuffle reduction; v' = A.v via 16 width-16 shuffles.
__global__ __launch_bounds__(256) void taps_kernel(
    const float* __restrict__ A, const float* __restrict__ B_ssm,
    const float* __restrict__ C_ssm)
{
    const int lane = threadIdx.x & 15;            // state index n
    const int c = blockIdx.x * 16 + (threadIdx.x >> 4);
    const float* Ac = A + (size_t)c * DS * DS + lane * DS;
    float arow[DS];
#pragma unroll
    for (int m = 0; m < DS; m++) arow[m] = Ac[m];
    float v  = B_ssm[c * DS + lane];
    float Cv = C_ssm[c * DS + lane];

    for (int j = 0; j < NTAPS; j++) {
        float y = Cv * v;
#pragma unroll
        for (int o = 8; o > 0; o >>= 1)
            y += __shfl_xor_sync(0xffffffffu, y, o, 16);
        if (lane == 0) d_taps[c * NTAPS + j] = y;
        float w = 0.f;
#pragma unroll
        for (int m = 0; m < DS; m++)
            w = fmaf(arow[m], __shfl_sync(0xffffffffu, v, m, 16), w);
        v = w;
    }
}

// ---------------------------------------------------------------- x f32 -> fp16
__global__ __launch_bounds__(256) void conv_x_kernel(const float* __restrict__ x)
{
    size_t idx = (size_t)blockIdx.x * 256 + threadIdx.x;   // one float4
    float4 v = *(const float4*)(x + idx * 4);
    __half2 h0 = __floats2half2_rn(v.x, v.y);
    __half2 h1 = __floats2half2_rn(v.z, v.w);
    uint2 pk = { *(uint32_t*)&h0, *(uint32_t*)&h1 };
    *(uint2*)((__half*)d_xh + idx * 4) = pk;
}

// ---------------------------------------------------------------- W [K][N]f32 -> [N][K]fp16
template<int WHICH, int K, int N>
__global__ void conv_w_kernel(const float* __restrict__ W)
{
    __shared__ float tb[32][33];
    __half* WT = (WHICH == 0 ? d_win_h : WHICH == 1 ? d_wg_h : d_wout_h);
    int n0 = blockIdx.x * 32, k0 = blockIdx.y * 32;
    int tx = threadIdx.x, ty = threadIdx.y;
#pragma unroll
    for (int i = ty; i < 32; i += 8)
        tb[i][tx] = W[(size_t)(k0 + i) * N + n0 + tx];
    __syncthreads();
#pragma unroll
    for (int j = ty; j < 32; j += 8)
        WT[(size_t)(n0 + j) * K + k0 + tx] = __float2half_rn(tb[tx][j]);
}

// ---------------------------------------------------------------- FIR + gate (all fp16 I/O, m-major)
__global__ __launch_bounds__(256) void fir_kernel()
{
    __shared__ float sx[288][33];       // [32 halo + 256][c]
    __shared__ float st[32][33];        // taps[c][j]
    const int t = threadIdx.x;
    const int c0 = blockIdx.y * 32, b = blockIdx.z;
    const int s0 = blockIdx.x * 256;
    const size_t rowbase = (size_t)b * SEQ;

    for (int idx = t; idx < 288 * 32; idx += 256) {
        int z = idx >> 5, c = idx & 31;
        int s = s0 - 32 + z;
        float v = 0.f;
        if (s >= 0) v = __half2float(d_xp16[(rowbase + s) * DI + c0 + c]);
        sx[z][c] = v;
    }
    for (int idx = t; idx < 32 * 32; idx += 256) {
        int r = idx >> 5, j = idx & 31;
        st[r][j] = d_taps[(c0 + r) * NTAPS + j];
    }
    __syncthreads();

    const int c  = t & 31;
    const int sb = (t >> 5) * 32;
    float k[NTAPS];
#pragma unroll
    for (int j = 0; j < NTAPS; j++) k[j] = st[c][j];

#pragma unroll
    for (int ch = 0; ch < 4; ch++) {
        const int sc = sb + ch * 8;
        float w[39];
#pragma unroll
        for (int z = 0; z < 39; z++) w[z] = sx[sc + 1 + z][c];
        float acc[8];
#pragma unroll
        for (int i = 0; i < 8; i++) acc[i] = 0.f;
#pragma unroll
        for (int j = 0; j < NTAPS; j++)
#pragma unroll
            for (int i = 0; i < 8; i++)
                acc[i] = fmaf(k[j], w[31 + i - j], acc[i]);
#pragma unroll
        for (int i = 0; i < 8; i++) {
            size_t row = rowbase + s0 + sc + i;
            float gv = __half2float(d_g16[row * DI + c0 + c]);
            d_yh[row * DI + c0 + c] = __float2half_rn(acc[i] * gv);
        }
    }
}

// ---------------------------------------------------------------- mma.sync GEMM (fp16)
// C[128x128] per CTA. A [M][K] fp16, B [N][K] fp16.
// BK=64 (128B rows, XOR-8 swizzle), 3-stage cp.async, 8 warps 64x32, 2 CTA/SM.
// Two __syncthreads per mainloop iteration (empirically fastest).
#define BKB        128
#define STAGE_B    32768
#define NSTAGE     3
#define SMEM_GEMM  (NSTAGE * STAGE_B)

template<int KBASE>
__device__ __forceinline__ void load_stage(uint32_t sb, int slot,
                                           const char* Ac, const char* Bc)
{
    const int ld = KBASE * 2;
    uint32_t sA = sb + slot * STAGE_B;
    uint32_t sB = sA + 16384;
    const int t = threadIdx.x;
#pragma unroll
    for (int it = 0; it < 4; it++) {
        int idx = t + it * 256;
        int r = idx >> 3, c = idx & 7;
        cpa16(sA + r * BKB + ((c ^ (r & 7)) << 4), Ac + (size_t)r * ld + c * 16);
    }
#pragma unroll
    for (int it = 0; it < 4; it++) {
        int idx = t + it * 256;
        int r = idx >> 3, c = idx & 7;
        cpa16(sB + r * BKB + ((c ^ (r & 7)) << 4), Bc + (size_t)r * ld + c * 16);
    }
}

// EPI 0: A=d_xh, B=d_win_h/d_wg_h (dual), writes d_xp16 / d_g16 (m-major fp16).
// EPI 1: A=d_yh, B=d_wout_h, writes f32 out rows.
template<int EPI, int KBASE>
__global__ __launch_bounds__(256, 2) void gemm_mma(
    const float* __restrict__ bias0, const float* __restrict__ bias1,
    float* __restrict__ outp)
{
    extern __shared__ char smem[];
    uint32_t sb = smem_u32(smem);
    const int t   = threadIdx.x;
    const int wid = t >> 5, lid = t & 31;
    const int NKC = KBASE / 64;

    int sel, n0;
    const __half* Aglob;
    const __half* B;
    const float* bias;
    if (EPI == 0) {
        Aglob = d_xh;
        sel = (blockIdx.x >= DI / 128);
        n0  = (blockIdx.x & (DI / 128 - 1)) * 128;
        B = sel ? d_wg_h : d_win_h;
        bias = sel ? bias1 : bias0;
    } else {
        Aglob = d_yh;
        sel = 0;
        n0  = blockIdx.x * 128;
        B = d_wout_h;
        bias = bias0;
    }
    const int m0 = blockIdx.y * 128;
    const char* Abase = (const char*)(Aglob + (size_t)m0 * KBASE);
    const char* Bbase = (const char*)(B + (size_t)n0 * KBASE);

#pragma unroll
    for (int p = 0; p < NSTAGE - 1; p++) {
        load_stage<KBASE>(sb, p, Abase + p * 128, Bbase + p * 128);
        CP_COMMIT();
    }

    const int wm = (wid & 1) * 64;
    const int wn = (wid >> 1) * 32;

    float acc[4][4][4];
#pragma unroll
    for (int i = 0; i < 4; i++)
#pragma unroll
        for (int j = 0; j < 4; j++)
#pragma unroll
            for (int q = 0; q < 4; q++) acc[i][j][q] = 0.f;

    int slot = 0, slot_ld = NSTAGE - 1;
    for (int i = 0; i < NKC; i++) {
        cp_wait<NSTAGE - 2>();
        __syncthreads();
        int j = i + NSTAGE - 1;
        if (j < NKC) {
            load_stage<KBASE>(sb, slot_ld, Abase + j * 128, Bbase + j * 128);
        }
        CP_COMMIT();
        if (++slot_ld == NSTAGE) slot_ld = 0;

        uint32_t sA = sb + slot * STAGE_B;
        uint32_t sB = sA + 16384;
        if (++slot == NSTAGE) slot = 0;
#pragma unroll
        for (int kk = 0; kk < 4; kk++) {
            uint32_t a[4][4], b[2][4];
#pragma unroll
            for (int mi = 0; mi < 4; mi++) {
                int row = wm + mi * 16 + (lid & 15);
                int ch  = kk * 2 + (lid >> 4);
                ldmx4(a[mi], sA + row * BKB + ((ch ^ (row & 7)) << 4));
            }
#pragma unroll
            for (int bi = 0; bi < 2; bi++) {
                int row = wn + bi * 16 + (lid & 15);
                int ch  = kk * 2 + (lid >> 4);
                ldmx4(b[bi], sB + row * BKB + ((ch ^ (row & 7)) << 4));
            }
#pragma unroll
            for (int mi = 0; mi < 4; mi++) {
#pragma unroll
                for (int bi = 0; bi < 2; bi++) {
                    mma16816(acc[mi][bi * 2 + 0], a[mi], b[bi][0], b[bi][2]);
                    mma16816(acc[mi][bi * 2 + 1], a[mi], b[bi][1], b[bi][3]);
                }
            }
        }
        __syncthreads();
    }

    // ---- epilogue ----
    const int q4 = lid & 3;
    const int r8 = lid >> 2;

    if (EPI == 0) {
        __half* dst = sel ? d_g16 : d_xp16;
#pragma unroll
        for (int mi = 0; mi < 4; mi++) {
#pragma unroll
            for (int ni = 0; ni < 4; ni++) {
                int n = n0 + wn + ni * 8 + 2 * q4;
                float bz0 = bias[n], bz1 = bias[n + 1];
#pragma unroll
                for (int rr = 0; rr < 2; rr++) {
                    int m = m0 + wm + mi * 16 + r8 + rr * 8;
                    float v0 = acc[mi][ni][rr * 2 + 0] + bz0;
                    float v1 = acc[mi][ni][rr * 2 + 1] + bz1;
                    if (sel) {
                        v0 = 1.f / (1.f + __expf(-v0));
                        v1 = 1.f / (1.f + __expf(-v1));
                    }
                    __half2 h2 = __floats2half2_rn(v0, v1);
                    *(__half2*)(dst + (size_t)m * DI + n) = h2;
                }
            }
        }
    } else {
#pragma unroll
        for (int mi = 0; mi < 4; mi++) {
#pragma unroll
            for (int ni = 0; ni < 4; ni++) {
                int n = n0 + wn + ni * 8 + 2 * q4;
                float bz0 = bias[n], bz1 = bias[n + 1];
#pragma unroll
                for (int rr = 0; rr < 2; rr++) {
                    int m = m0 + wm + mi * 16 + r8 + rr * 8;
                    float2 v;
                    v.x = acc[mi][ni][rr * 2 + 0] + bz0;
                    v.y = acc[mi][ni][rr * 2 + 1] + bz1;
                    *(float2*)(outp + (size_t)m * DM + n) = v;
                }
            }
        }
    }
}

// ---------------------------------------------------------------- launch
extern "C" void kernel_launch(void* const* d_in, const int* in_sizes, int n_in,
                              void* d_out, int out_size)
{
    const float* x      = (const float*)d_in[0];
    const float* w_in   = (const float*)d_in[1];
    const float* b_in   = (const float*)d_in[2];
    const float* w_gate = (const float*)d_in[3];
    const float* b_gate = (const float*)d_in[4];
    const float* A      = (const float*)d_in[5];
    const float* B_ssm  = (const float*)d_in[6];
    const float* C_ssm  = (const float*)d_in[7];
    const float* w_out  = (const float*)d_in[8];
    const float* b_out  = (const float*)d_in[9];
    float* out = (float*)d_out;

    static cudaStream_t s1 = nullptr, s2 = nullptr, s3 = nullptr;
    static cudaEvent_t evf = nullptr, ev1 = nullptr, ev2 = nullptr, ev3 = nullptr;
    static bool init_done = false;
    if (!init_done) {
        cudaFuncSetAttribute(gemm_mma<0, DM>,
                             cudaFuncAttributeMaxDynamicSharedMemorySize, SMEM_GEMM);
        cudaFuncSetAttribute(gemm_mma<1, DI>,
                             cudaFuncAttributeMaxDynamicSharedMemorySize, SMEM_GEMM);
        cudaStreamCreateWithFlags(&s1, cudaStreamNonBlocking);
        cudaStreamCreateWithFlags(&s2, cudaStreamNonBlocking);
        cudaStreamCreateWithFlags(&s3, cudaStreamNonBlocking);
        cudaEventCreateWithFlags(&evf, cudaEventDisableTiming);
        cudaEventCreateWithFlags(&ev1, cudaEventDisableTiming);
        cudaEventCreateWithFlags(&ev2, cudaEventDisableTiming);
        cudaEventCreateWithFlags(&ev3, cudaEventDisableTiming);
        init_done = true;
    }

    // fork side streams off the (per-thread default) capture stream
    cudaEventRecord(evf, cudaStreamPerThread);
    cudaStreamWaitEvent(s1, evf, 0);
    cudaStreamWaitEvent(s2, evf, 0);
    cudaStreamWaitEvent(s3, evf, 0);

    // prep: conv_x on main stream; w_in/w_gate on s1/s2 (gate gemm0);
    // w_out + taps on s3 (NOT needed until fir/gemm2 — join deferred past gemm0)
    conv_w_kernel<0, DM, DI><<<dim3(DI / 32, DM / 32), dim3(32, 8), 0, s1>>>(w_in);
    conv_w_kernel<1, DM, DI><<<dim3(DI / 32, DM / 32), dim3(32, 8), 0, s2>>>(w_gate);
    conv_w_kernel<2, DI, DM><<<dim3(DM / 32, DI / 32), dim3(32, 8), 0, s3>>>(w_out);
    taps_kernel<<<DI / 16, 256, 0, s3>>>(A, B_ssm, C_ssm);
    conv_x_kernel<<<(BATCH * SEQ * DM / 4) / 256, 256>>>(x);

    // join s1/s2 before gemm0 (its inputs)
    cudaEventRecord(ev1, s1);
    cudaEventRecord(ev2, s2);
    cudaStreamWaitEvent(cudaStreamPerThread, ev1, 0);
    cudaStreamWaitEvent(cudaStreamPerThread, ev2, 0);

    gemm_mma<0, DM><<<dim3(2 * DI / 128, BATCH * SEQ / 128), 256, SMEM_GEMM>>>(
        b_in, b_gate, nullptr);

    // join s3 (taps + w_out) before fir; overlaps with gemm0
    cudaEventRecord(ev3, s3);
    cudaStreamWaitEvent(cudaStreamPerThread, ev3, 0);

    fir_kernel<<<dim3(SEQ / 256, DI / 32, BATCH), 256>>>();

    gemm_mma<1, DI><<<dim3(DM / 128, BATCH * SEQ / 128), 256, SMEM_GEMM>>>(
        b_out, nullptr, out);
}